// round 14
// baseline (speedup 1.0000x reference)
#include <cuda_runtime.h>
#include <cuda_fp16.h>
#include <cstdint>
#include <math.h>

// ---------------- problem constants ----------------
#define N_IMG  64
#define A_CH   512      // K
#define M_POSE 512
#define M_TOT  544
#define HW     1024

// ---------------- GEMM tiling ----------------
#define BM 128
#define BN 256
#define BK 32
#define NCH (A_CH / BK)   // 16
#define NTHR 256          // 8 warps

// smem:
// A tile (fp16): 128 rows x 32 halves, row stride 40 halves (80 B) -> proven conflict-free ldmatrix
// B tile (fp32): 32 rows x 256 floats, row stride 260 floats (1040 B);
//   frag LDS bank = (2*k*260 + n) mod 32 spans all 32 banks (260 mod 16 = 4) -> conflict-free
#define ASTRH 40
#define BSTRF 260
#define A_ROW_B (ASTRH * 2)       // 80
#define B_ROW_B (BSTRF * 4)       // 1040
#define A_TILE_B (BM * A_ROW_B)   // 10240
#define B_TILE_B (BK * B_ROW_B)   // 33280
#define OFF_A 0
#define OFF_B (A_TILE_B)
#define STG_B (A_TILE_B + B_TILE_B)   // 43520
#define NSTAGE 3
#define SMEM_MAIN (NSTAGE * STG_B)    // 130560

// ---------------- device-global scratch ----------------
__device__ __half g_W[M_TOT * A_CH];   // fp16 weights (pose ++ act)
__device__ float  g_bias[M_TOT];

// ---------------- PTX helpers ----------------
__device__ __forceinline__ uint32_t s2u(const void* p) {
    uint32_t a;
    asm("{ .reg .u64 t; cvta.to.shared.u64 t, %1; cvt.u32.u64 %0, t; }" : "=r"(a) : "l"(p));
    return a;
}
__device__ __forceinline__ void cp16(uint32_t dst, const void* src) {
    asm volatile("cp.async.cg.shared.global [%0], [%1], 16;\n" :: "r"(dst), "l"(src));
}
#define CP_COMMIT() asm volatile("cp.async.commit_group;\n" ::: "memory")
#define CP_WAIT(n)  asm volatile("cp.async.wait_group %0;\n" :: "n"(n) : "memory")

#define LDSM4(r, addr)                                                          \
    asm volatile("ldmatrix.sync.aligned.m8n8.x4.shared.b16 {%0,%1,%2,%3},[%4];" \
                 : "=r"((r)[0]), "=r"((r)[1]), "=r"((r)[2]), "=r"((r)[3])       \
                 : "r"(addr))

#define MMA_F16(d, a, b0, b1)                                                   \
    asm volatile("mma.sync.aligned.m16n8k16.row.col.f32.f16.f16.f32 "           \
                 "{%0,%1,%2,%3},{%4,%5,%6,%7},{%8,%9},{%0,%1,%2,%3};"           \
                 : "+f"((d)[0]), "+f"((d)[1]), "+f"((d)[2]), "+f"((d)[3])       \
                 : "r"((a)[0]), "r"((a)[1]), "r"((a)[2]), "r"((a)[3]),          \
                   "r"(b0), "r"(b1))

__device__ __forceinline__ uint32_t lds32(uint32_t addr) {
    uint32_t v;
    asm volatile("ld.shared.b32 %0, [%1];" : "=r"(v) : "r"(addr));
    return v;
}
// pack {lo, hi} floats -> f16x2 register (lo in bits [0:16))
__device__ __forceinline__ uint32_t pack_h2(uint32_t lo_f32_bits, uint32_t hi_f32_bits) {
    uint32_t r;
    asm("cvt.rn.f16x2.f32 %0, %1, %2;"
        : "=r"(r) : "f"(__uint_as_float(hi_f32_bits)), "f"(__uint_as_float(lo_f32_bits)));
    return r;
}

// ---------------- prep: pack W (pose ++ act) -> fp16, bias ----------------
__global__ void pack_w(const float* __restrict__ Wp, const float* __restrict__ bp,
                       const float* __restrict__ Wa, const float* __restrict__ ba) {
    int i = blockIdx.x * blockDim.x + threadIdx.x;
    if (i < M_TOT * A_CH) {
        int o = i >> 9;
        int a = i & 511;
        float v = (o < M_POSE) ? Wp[o * A_CH + a] : Wa[(o - M_POSE) * A_CH + a];
        g_W[i] = __float2half_rn(v);
    }
    if (i < M_TOT)
        g_bias[i] = (i < M_POSE) ? bp[i] : ba[i - M_POSE];
}

// ---------------- fused GEMM: pose tiles (bx<4) + act tile (bx==4), fp16 single pass ----------------
// grid (5, 4, 64), 256 threads = 8 warps
__global__ __launch_bounds__(NTHR, 1) void caps_mma(const float* __restrict__ x,
                                                    float* __restrict__ out) {
    extern __shared__ char smem[];
    const uint32_t sb = s2u(smem);
    const int tid  = threadIdx.x;
    const int lane = tid & 31, wid = tid >> 5;
    const int hw0 = blockIdx.y * BN;
    const int img = blockIdx.z;
    const bool is_act_cta = (blockIdx.x == 4);
    const int m0 = is_act_cta ? M_POSE : blockIdx.x * BM;

    const char* wptr = (const char*)(g_W + (size_t)m0 * A_CH);   // fp16, row = 1024 B
    const char* xptr = (const char*)(x + (size_t)img * A_CH * HW + hw0);

    // B-tile loader (32 rows x 1024 B fp32): 8 cp16/thread
#define ISSUE_B(s_, kof)                                                        \
    do {                                                                        \
        _Pragma("unroll")                                                       \
        for (int j = 0; j < 8; ++j) {                                           \
            int idx = tid + j * NTHR;                                           \
            int r = idx >> 6, c = idx & 63;                                     \
            uint32_t so = r * B_ROW_B + c * 16;                                 \
            size_t go = (((kof) + r) * (size_t)HW + c * 4) * 4;                 \
            cp16((s_) + OFF_B + so, xptr + go);                                 \
        }                                                                       \
    } while (0)

    if (!is_act_cta) {
        // ============ pose branch: 128 x 256, warp grid 2M x 4N, warp tile 64x64 ============
        const int wm = wid & 1, wn = wid >> 1;   // wn 0..3

        // A loader: 128 rows x 64 B fp16 -> 2 cp16/thread
#define ISSUE(stage, ch)                                                        \
    do {                                                                        \
        uint32_t s_ = sb + (stage) * STG_B;                                     \
        size_t kof = (size_t)(ch) * BK;                                         \
        _Pragma("unroll")                                                       \
        for (int j = 0; j < 2; ++j) {                                           \
            int idx = tid + j * NTHR;                                           \
            int r = idx >> 2, c = idx & 3;                                      \
            uint32_t so = r * A_ROW_B + c * 16;                                 \
            size_t go = ((size_t)r * A_CH + kof) * 2 + c * 16;                  \
            cp16(s_ + OFF_A + so, wptr + go);                                   \
        }                                                                       \
        ISSUE_B(s_, kof);                                                       \
        CP_COMMIT();                                                            \
    } while (0)

        float acc[4][8][4];
#pragma unroll
        for (int i = 0; i < 4; ++i)
#pragma unroll
            for (int j = 0; j < 8; ++j)
#pragma unroll
                for (int k = 0; k < 4; ++k) acc[i][j][k] = 0.f;

        // A ldmatrix lane address (R10-proven mapping for 16-bit A, k16 frags)
        const uint32_t aLane = (uint32_t)((wm * 64 + (lane & 15)) * A_ROW_B + (lane >> 4) * 16);
        // B frag base: k0 = (lane&3)*2, n = wn*64 + lane>>2
        const uint32_t bLane = (uint32_t)((((lane & 3) * 2) * BSTRF + wn * 64 + (lane >> 2)) * 4);

        ISSUE(0, 0);
        ISSUE(1, 1);

        for (int ch = 0; ch < NCH; ++ch) {
            if (ch == NCH - 1) CP_WAIT(0); else CP_WAIT(1);
            __syncthreads();
            if (ch + 2 < NCH) ISSUE((ch + 2) % NSTAGE, ch + 2);

            const uint32_t s_ = sb + (ch % NSTAGE) * STG_B;
#pragma unroll
            for (int k16 = 0; k16 < 2; ++k16) {
                // B fragments: 8 n8-tiles x 2 regs; each reg = two k-consecutive f32 -> f16x2
                uint32_t bf[8][2];
                const uint32_t bb = s_ + OFF_B + bLane + k16 * 16 * B_ROW_B;
#pragma unroll
                for (int nt = 0; nt < 8; ++nt) {
                    uint32_t a0 = lds32(bb + nt * 32);
                    uint32_t a1 = lds32(bb + nt * 32 + B_ROW_B);
                    uint32_t a8 = lds32(bb + nt * 32 + 8 * B_ROW_B);
                    uint32_t a9 = lds32(bb + nt * 32 + 9 * B_ROW_B);
                    bf[nt][0] = pack_h2(a0, a1);
                    bf[nt][1] = pack_h2(a8, a9);
                }
                // A fragments: 4 m16 tiles (fp16) via ldmatrix
                uint32_t af[4][4];
#pragma unroll
                for (int mt = 0; mt < 4; ++mt) {
                    uint32_t aAddr = s_ + OFF_A + aLane + mt * 16 * A_ROW_B + k16 * 32;
                    LDSM4(af[mt], aAddr);
                }
#pragma unroll
                for (int mt = 0; mt < 4; ++mt)
#pragma unroll
                    for (int j = 0; j < 8; ++j)
                        MMA_F16(acc[mt][j], af[mt], bf[j][0], bf[j][1]);
            }
        }
#undef ISSUE

        const int hwBase = hw0 + wn * 64 + (lane & 3) * 2;
#pragma unroll
        for (int mt = 0; mt < 4; ++mt) {
#pragma unroll
            for (int rr = 0; rr < 2; ++rr) {
                const int m = m0 + wm * 64 + mt * 16 + (lane >> 2) + rr * 8;
                const float bias = g_bias[m];
                float* rowp = out + ((size_t)img * M_POSE + m) * HW;
#pragma unroll
                for (int j = 0; j < 8; ++j) {
                    float2 v;
                    v.x = acc[mt][j][rr * 2 + 0] + bias;
                    v.y = acc[mt][j][rr * 2 + 1] + bias;
                    *reinterpret_cast<float2*>(rowp + hwBase + j * 8) = v;
                }
            }
        }
    } else {
        // ============ act branch: 32 x 256 + sigmoid; 8 warps, warp tile 32x32 ============
#define AISSUE(stage, ch)                                                       \
    do {                                                                        \
        uint32_t s_ = sb + (stage) * STG_B;                                     \
        size_t kof = (size_t)(ch) * BK;                                         \
        if (tid < 128) {                                                        \
            int r = tid >> 2, c = tid & 3;                                      \
            uint32_t so = r * A_ROW_B + c * 16;                                 \
            size_t go = ((size_t)r * A_CH + kof) * 2 + c * 16;                  \
            cp16(s_ + OFF_A + so, wptr + go);                                   \
        }                                                                       \
        ISSUE_B(s_, kof);                                                       \
        CP_COMMIT();                                                            \
    } while (0)

        float acc[2][4][4];
#pragma unroll
        for (int i = 0; i < 2; ++i)
#pragma unroll
            for (int j = 0; j < 4; ++j)
#pragma unroll
                for (int k = 0; k < 4; ++k) acc[i][j][k] = 0.f;

        const uint32_t aLane = (uint32_t)((lane & 15) * A_ROW_B + (lane >> 4) * 16);
        const uint32_t bLane = (uint32_t)((((lane & 3) * 2) * BSTRF + wid * 32 + (lane >> 2)) * 4);

        AISSUE(0, 0);
        AISSUE(1, 1);

        for (int ch = 0; ch < NCH; ++ch) {
            if (ch == NCH - 1) CP_WAIT(0); else CP_WAIT(1);
            __syncthreads();
            if (ch + 2 < NCH) AISSUE((ch + 2) % NSTAGE, ch + 2);

            const uint32_t s_ = sb + (ch % NSTAGE) * STG_B;
#pragma unroll
            for (int k16 = 0; k16 < 2; ++k16) {
                uint32_t bf[4][2];
                const uint32_t bb = s_ + OFF_B + bLane + k16 * 16 * B_ROW_B;
#pragma unroll
                for (int nt = 0; nt < 4; ++nt) {
                    uint32_t a0 = lds32(bb + nt * 32);
                    uint32_t a1 = lds32(bb + nt * 32 + B_ROW_B);
                    uint32_t a8 = lds32(bb + nt * 32 + 8 * B_ROW_B);
                    uint32_t a9 = lds32(bb + nt * 32 + 9 * B_ROW_B);
                    bf[nt][0] = pack_h2(a0, a1);
                    bf[nt][1] = pack_h2(a8, a9);
                }
                uint32_t af[2][4];
#pragma unroll
                for (int mt = 0; mt < 2; ++mt) {
                    uint32_t aAddr = s_ + OFF_A + aLane + mt * 16 * A_ROW_B + k16 * 32;
                    LDSM4(af[mt], aAddr);
                }
#pragma unroll
                for (int mt = 0; mt < 2; ++mt)
#pragma unroll
                    for (int j = 0; j < 4; ++j)
                        MMA_F16(acc[mt][j], af[mt], bf[j][0], bf[j][1]);
            }
        }
#undef AISSUE

        const int hwBase = hw0 + wid * 32 + (lane & 3) * 2;
        float* actout = out + (size_t)N_IMG * M_POSE * HW;
#pragma unroll
        for (int mt = 0; mt < 2; ++mt) {
#pragma unroll
            for (int rr = 0; rr < 2; ++rr) {
                const int m = mt * 16 + (lane >> 2) + rr * 8;   // 0..31
                const float bias = g_bias[M_POSE + m];
                float* rowp = actout + ((size_t)img * (M_TOT - M_POSE) + m) * HW;
#pragma unroll
                for (int j = 0; j < 4; ++j) {
                    float2 v;
                    v.x = acc[mt][j][rr * 2 + 0] + bias;
                    v.y = acc[mt][j][rr * 2 + 1] + bias;
                    v.x = 1.f / (1.f + __expf(-v.x));
                    v.y = 1.f / (1.f + __expf(-v.y));
                    *reinterpret_cast<float2*>(rowp + hwBase + j * 8) = v;
                }
            }
        }
    }
#undef ISSUE_B
}

// ---------------- launch ----------------
extern "C" void kernel_launch(void* const* d_in, const int* in_sizes, int n_in,
                              void* d_out, int out_size) {
    const float* x  = (const float*)d_in[0];  // [64, 512, 32, 32]
    const float* Wp = (const float*)d_in[1];  // [512, 512]
    const float* bp = (const float*)d_in[2];  // [512]
    const float* Wa = (const float*)d_in[3];  // [32, 512]
    const float* ba = (const float*)d_in[4];  // [32]
    float* out = (float*)d_out;

    pack_w<<<(M_TOT * A_CH + 255) / 256, 256>>>(Wp, bp, Wa, ba);

    cudaFuncSetAttribute(caps_mma, cudaFuncAttributeMaxDynamicSharedMemorySize, SMEM_MAIN);
    caps_mma<<<dim3(5, HW / BN, N_IMG), NTHR, SMEM_MAIN>>>(x, out);
}

// round 16
// speedup vs baseline: 1.5728x; 1.5728x over previous
#include <cuda_runtime.h>
#include <cuda_fp16.h>
#include <cstdint>
#include <math.h>

// ---------------- problem constants ----------------
#define N_IMG  64
#define A_CH   512      // K
#define M_POSE 512
#define M_TOT  544
#define HW     1024

// ---------------- GEMM tiling (R9-proven geometry, single fp16 pass) ----------------
#define BM 128
#define BN 256
#define BK 32
#define NCH (A_CH / BK)   // 16
#define NTHR 256          // 8 warps

// smem (fp16 data, R9-proven conflict-free strides):
// A tile: 128 rows x 32 halves, row stride 40 halves (80 B)
// B tile: 32 rows x 256 halves, row stride 264 halves (528 B)
#define ASTRH 40
#define BSTRH 264
#define A_ROW_B (ASTRH * 2)       // 80
#define B_ROW_B (BSTRH * 2)       // 528
#define A_TILE_B (BM * A_ROW_B)   // 10240
#define B_TILE_B (BK * B_ROW_B)   // 16896
#define OFF_A 0
#define OFF_B (A_TILE_B)
#define STG_B (A_TILE_B + B_TILE_B)   // 27136
#define NSTAGE 3
#define SMEM_MAIN (NSTAGE * STG_B)    // 81408

// ---------------- device-global scratch ----------------
__device__ __half g_W[M_TOT * A_CH];                 // fp16 weights (pose ++ act)
__device__ float  g_bias[M_TOT];
__device__ __half g_xh[(size_t)N_IMG * A_CH * HW];   // fp16 x, same layout

// ---------------- PTX helpers ----------------
__device__ __forceinline__ uint32_t s2u(const void* p) {
    uint32_t a;
    asm("{ .reg .u64 t; cvta.to.shared.u64 t, %1; cvt.u32.u64 %0, t; }" : "=r"(a) : "l"(p));
    return a;
}
__device__ __forceinline__ void cp16(uint32_t dst, const void* src) {
    asm volatile("cp.async.cg.shared.global [%0], [%1], 16;\n" :: "r"(dst), "l"(src));
}
#define CP_COMMIT() asm volatile("cp.async.commit_group;\n" ::: "memory")
#define CP_WAIT(n)  asm volatile("cp.async.wait_group %0;\n" :: "n"(n) : "memory")

#define LDSM4(r, addr)                                                          \
    asm volatile("ldmatrix.sync.aligned.m8n8.x4.shared.b16 {%0,%1,%2,%3},[%4];" \
                 : "=r"((r)[0]), "=r"((r)[1]), "=r"((r)[2]), "=r"((r)[3])       \
                 : "r"(addr))
#define LDSM4T(r, addr)                                                         \
    asm volatile("ldmatrix.sync.aligned.m8n8.x4.trans.shared.b16 {%0,%1,%2,%3},[%4];" \
                 : "=r"((r)[0]), "=r"((r)[1]), "=r"((r)[2]), "=r"((r)[3])       \
                 : "r"(addr))
#define MMA_F16(d, a, b0, b1)                                                   \
    asm volatile("mma.sync.aligned.m16n8k16.row.col.f32.f16.f16.f32 "           \
                 "{%0,%1,%2,%3},{%4,%5,%6,%7},{%8,%9},{%0,%1,%2,%3};"           \
                 : "+f"((d)[0]), "+f"((d)[1]), "+f"((d)[2]), "+f"((d)[3])       \
                 : "r"((a)[0]), "r"((a)[1]), "r"((a)[2]), "r"((a)[3]),          \
                   "r"(b0), "r"(b1))

// ---------------- prep 1: pack W (pose ++ act) -> fp16, bias ----------------
__global__ void pack_w(const float* __restrict__ Wp, const float* __restrict__ bp,
                       const float* __restrict__ Wa, const float* __restrict__ ba) {
    int i = blockIdx.x * blockDim.x + threadIdx.x;
    if (i < M_TOT * A_CH) {
        int o = i >> 9;
        int a = i & 511;
        float v = (o < M_POSE) ? Wp[o * A_CH + a] : Wa[(o - M_POSE) * A_CH + a];
        g_W[i] = __float2half_rn(v);
    }
    if (i < M_TOT)
        g_bias[i] = (i < M_POSE) ? bp[i] : ba[i - M_POSE];
}

// ---------------- prep 2: x fp32 -> fp16 (8 elems/thread, 16B stores) ----------------
__global__ __launch_bounds__(256) void conv_x(const float4* __restrict__ x) {
    size_t i = ((size_t)blockIdx.x * blockDim.x + threadIdx.x) * 2;   // 2 float4 = 8 floats
    float4 v0 = x[i], v1 = x[i + 1];
    __half2 h[4];
    h[0] = __floats2half2_rn(v0.x, v0.y);
    h[1] = __floats2half2_rn(v0.z, v0.w);
    h[2] = __floats2half2_rn(v1.x, v1.y);
    h[3] = __floats2half2_rn(v1.z, v1.w);
    *reinterpret_cast<uint4*>(&g_xh[i * 4]) = *reinterpret_cast<uint4*>(h);
}

// ---------------- fused GEMM: pose tiles (bx<4) + act tile (bx==4), fp16 single pass ----------------
// grid (5, 4, 64), 256 threads = 8 warps
__global__ __launch_bounds__(NTHR, 1) void caps_mma(float* __restrict__ out) {
    extern __shared__ char smem[];
    const uint32_t sb = s2u(smem);
    const int tid  = threadIdx.x;
    const int lane = tid & 31, wid = tid >> 5;
    const int hw0 = blockIdx.y * BN;
    const int img = blockIdx.z;
    const bool is_act_cta = (blockIdx.x == 4);
    const int m0 = is_act_cta ? M_POSE : blockIdx.x * BM;

    const char* wptr = (const char*)(g_W + (size_t)m0 * A_CH);             // row = 1024 B
    const char* xptr = (const char*)(g_xh + (size_t)img * A_CH * HW + hw0);// row = 2048 B

    // B-tile loader: 32 rows x 512 B fp16 -> 4 cp16/thread
#define ISSUE_B(s_, kof)                                                        \
    do {                                                                        \
        _Pragma("unroll")                                                       \
        for (int j = 0; j < 4; ++j) {                                           \
            int idx = tid + j * NTHR;                                           \
            int r = idx >> 5, c = idx & 31;                                     \
            uint32_t so = r * B_ROW_B + c * 16;                                 \
            size_t go = (((kof) + r) * (size_t)HW + c * 8) * 2;                 \
            cp16((s_) + OFF_B + so, xptr + go);                                 \
        }                                                                       \
    } while (0)

    if (!is_act_cta) {
        // ============ pose branch: 128 x 256, warp grid 2M x 4N, warp tile 64x64 ============
        const int wm = wid & 1, wn = wid >> 1;   // wn 0..3

        // A loader: 128 rows x 64 B fp16 -> 2 cp16/thread
#define ISSUE(stage, ch)                                                        \
    do {                                                                        \
        uint32_t s_ = sb + (stage) * STG_B;                                     \
        size_t kof = (size_t)(ch) * BK;                                         \
        _Pragma("unroll")                                                       \
        for (int j = 0; j < 2; ++j) {                                           \
            int idx = tid + j * NTHR;                                           \
            int r = idx >> 2, c = idx & 3;                                      \
            uint32_t so = r * A_ROW_B + c * 16;                                 \
            size_t go = ((size_t)r * A_CH + kof) * 2 + c * 16;                  \
            cp16(s_ + OFF_A + so, wptr + go);                                   \
        }                                                                       \
        ISSUE_B(s_, kof);                                                       \
        CP_COMMIT();                                                            \
    } while (0)

        float acc[4][8][4];
#pragma unroll
        for (int i = 0; i < 4; ++i)
#pragma unroll
            for (int j = 0; j < 8; ++j)
#pragma unroll
                for (int k = 0; k < 4; ++k) acc[i][j][k] = 0.f;

        // R9-proven lane mappings
        const uint32_t aLane = (uint32_t)((wm * 64 + (lane & 15)) * A_ROW_B + (lane >> 4) * 16);
        const uint32_t bLane = (uint32_t)((lane & 15) * B_ROW_B + (wn * 64 + (lane >> 4) * 8) * 2);

        ISSUE(0, 0);
        ISSUE(1, 1);

        for (int ch = 0; ch < NCH; ++ch) {
            if (ch == NCH - 1) CP_WAIT(0); else CP_WAIT(1);
            __syncthreads();
            if (ch + 2 < NCH) ISSUE((ch + 2) % NSTAGE, ch + 2);

            const uint32_t s_ = sb + (ch % NSTAGE) * STG_B;
#pragma unroll
            for (int k16 = 0; k16 < 2; ++k16) {
                uint32_t af[4][4];
#pragma unroll
                for (int mt = 0; mt < 4; ++mt) {
                    uint32_t aAddr = s_ + OFF_A + aLane + mt * 16 * A_ROW_B + k16 * 32;
                    LDSM4(af[mt], aAddr);
                }
                uint32_t bh[16];
#pragma unroll
                for (int nt = 0; nt < 4; ++nt) {
                    uint32_t bAddr = s_ + OFF_B + bLane + k16 * 16 * B_ROW_B + nt * 32;
                    LDSM4T(bh + nt * 4, bAddr);
                }
#pragma unroll
                for (int mt = 0; mt < 4; ++mt)
#pragma unroll
                    for (int j = 0; j < 8; ++j) {
                        int bi = (j >> 1) * 4 + (j & 1) * 2;
                        MMA_F16(acc[mt][j], af[mt], bh[bi], bh[bi + 1]);
                    }
            }
        }
#undef ISSUE

        const int hwBase = hw0 + wn * 64 + (lane & 3) * 2;
#pragma unroll
        for (int mt = 0; mt < 4; ++mt) {
#pragma unroll
            for (int rr = 0; rr < 2; ++rr) {
                const int m = m0 + wm * 64 + mt * 16 + (lane >> 2) + rr * 8;
                const float bias = g_bias[m];
                float* rowp = out + ((size_t)img * M_POSE + m) * HW;
#pragma unroll
                for (int j = 0; j < 8; ++j) {
                    float2 v;
                    v.x = acc[mt][j][rr * 2 + 0] + bias;
                    v.y = acc[mt][j][rr * 2 + 1] + bias;
                    *reinterpret_cast<float2*>(rowp + hwBase + j * 8) = v;
                }
            }
        }
    } else {
        // ============ act branch: 32 x 256 + sigmoid; 8 warps, warp tile 32x32 ============
#define AISSUE(stage, ch)                                                       \
    do {                                                                        \
        uint32_t s_ = sb + (stage) * STG_B;                                     \
        size_t kof = (size_t)(ch) * BK;                                         \
        if (tid < 128) {                                                        \
            int r = tid >> 2, c = tid & 3;                                      \
            uint32_t so = r * A_ROW_B + c * 16;                                 \
            size_t go = ((size_t)r * A_CH + kof) * 2 + c * 16;                  \
            cp16(s_ + OFF_A + so, wptr + go);                                   \
        }                                                                       \
        ISSUE_B(s_, kof);                                                       \
        CP_COMMIT();                                                            \
    } while (0)

        float acc[2][4][4];
#pragma unroll
        for (int i = 0; i < 2; ++i)
#pragma unroll
            for (int j = 0; j < 4; ++j)
#pragma unroll
                for (int k = 0; k < 4; ++k) acc[i][j][k] = 0.f;

        const uint32_t aLane = (uint32_t)((lane & 15) * A_ROW_B + (lane >> 4) * 16);
        const uint32_t bLane = (uint32_t)((lane & 15) * B_ROW_B + (wid * 32 + (lane >> 4) * 8) * 2);

        AISSUE(0, 0);
        AISSUE(1, 1);

        for (int ch = 0; ch < NCH; ++ch) {
            if (ch == NCH - 1) CP_WAIT(0); else CP_WAIT(1);
            __syncthreads();
            if (ch + 2 < NCH) AISSUE((ch + 2) % NSTAGE, ch + 2);

            const uint32_t s_ = sb + (ch % NSTAGE) * STG_B;
#pragma unroll
            for (int k16 = 0; k16 < 2; ++k16) {
                uint32_t af[2][4];
#pragma unroll
                for (int mt = 0; mt < 2; ++mt) {
                    uint32_t aAddr = s_ + OFF_A + aLane + mt * 16 * A_ROW_B + k16 * 32;
                    LDSM4(af[mt], aAddr);
                }
                uint32_t bh[8];
#pragma unroll
                for (int nt = 0; nt < 2; ++nt) {
                    uint32_t bAddr = s_ + OFF_B + bLane + k16 * 16 * B_ROW_B + nt * 32;
                    LDSM4T(bh + nt * 4, bAddr);
                }
#pragma unroll
                for (int mt = 0; mt < 2; ++mt)
#pragma unroll
                    for (int j = 0; j < 4; ++j) {
                        int bi = (j >> 1) * 4 + (j & 1) * 2;
                        MMA_F16(acc[mt][j], af[mt], bh[bi], bh[bi + 1]);
                    }
            }
        }
#undef AISSUE

        const int hwBase = hw0 + wid * 32 + (lane & 3) * 2;
        float* actout = out + (size_t)N_IMG * M_POSE * HW;
#pragma unroll
        for (int mt = 0; mt < 2; ++mt) {
#pragma unroll
            for (int rr = 0; rr < 2; ++rr) {
                const int m = mt * 16 + (lane >> 2) + rr * 8;   // 0..31
                const float bias = g_bias[M_POSE + m];
                float* rowp = actout + ((size_t)img * (M_TOT - M_POSE) + m) * HW;
#pragma unroll
                for (int j = 0; j < 4; ++j) {
                    float2 v;
                    v.x = acc[mt][j][rr * 2 + 0] + bias;
                    v.y = acc[mt][j][rr * 2 + 1] + bias;
                    v.x = 1.f / (1.f + __expf(-v.x));
                    v.y = 1.f / (1.f + __expf(-v.y));
                    *reinterpret_cast<float2*>(rowp + hwBase + j * 8) = v;
                }
            }
        }
    }
#undef ISSUE_B
}

// ---------------- launch ----------------
extern "C" void kernel_launch(void* const* d_in, const int* in_sizes, int n_in,
                              void* d_out, int out_size) {
    const float* x  = (const float*)d_in[0];  // [64, 512, 32, 32]
    const float* Wp = (const float*)d_in[1];  // [512, 512]
    const float* bp = (const float*)d_in[2];  // [512]
    const float* Wa = (const float*)d_in[3];  // [32, 512]
    const float* ba = (const float*)d_in[4];  // [32]
    float* out = (float*)d_out;

    pack_w<<<(M_TOT * A_CH + 255) / 256, 256>>>(Wp, bp, Wa, ba);

    size_t total4 = (size_t)N_IMG * A_CH * HW / 4;   // float4 count
    conv_x<<<(unsigned)(total4 / 512), 256>>>((const float4*)x);

    cudaFuncSetAttribute(caps_mma, cudaFuncAttributeMaxDynamicSharedMemorySize, SMEM_MAIN);
    caps_mma<<<dim3(5, HW / BN, N_IMG), NTHR, SMEM_MAIN>>>(out);
}

// round 17
// speedup vs baseline: 1.9537x; 1.2422x over previous
#include <cuda_runtime.h>
#include <cuda_fp16.h>
#include <cstdint>
#include <math.h>

// ---------------- problem constants ----------------
#define N_IMG  64
#define A_CH   512      // K
#define M_POSE 512
#define M_TOT  544
#define HW     1024

// ---------------- GEMM tiling (R7 geometry, fp16 single pass, occupancy 2) ----------------
#define BM 128
#define BN 128
#define BK 32
#define NCH (A_CH / BK)   // 16
#define NTHR 256          // 8 warps

// smem (fp16): A rows 40 halves (80 B), B rows 136 halves (272 B) — R7-proven conflict-free
#define ASTRH 40
#define BSTRH 136
#define A_ROW_B (ASTRH * 2)       // 80
#define B_ROW_B (BSTRH * 2)       // 272
#define A_TILE_B (BM * A_ROW_B)   // 10240
#define B_TILE_B (BK * B_ROW_B)   // 8704
#define OFF_A 0
#define OFF_B (A_TILE_B)
#define STG_B (A_TILE_B + B_TILE_B)   // 18944
#define NSTAGE 3
#define SMEM_MAIN (NSTAGE * STG_B)    // 56832  -> 2 CTAs/SM

// ---------------- device-global scratch ----------------
__device__ __half g_W[M_TOT * A_CH];                 // fp16 weights (pose ++ act)
__device__ float  g_bias[M_TOT];
__device__ __half g_xh[(size_t)N_IMG * A_CH * HW];   // fp16 x, same layout

// ---------------- PTX helpers ----------------
__device__ __forceinline__ uint32_t s2u(const void* p) {
    uint32_t a;
    asm("{ .reg .u64 t; cvta.to.shared.u64 t, %1; cvt.u32.u64 %0, t; }" : "=r"(a) : "l"(p));
    return a;
}
__device__ __forceinline__ void cp16(uint32_t dst, const void* src) {
    asm volatile("cp.async.cg.shared.global [%0], [%1], 16;\n" :: "r"(dst), "l"(src));
}
#define CP_COMMIT() asm volatile("cp.async.commit_group;\n" ::: "memory")
#define CP_WAIT(n)  asm volatile("cp.async.wait_group %0;\n" :: "n"(n) : "memory")

#define LDSM4(r, addr)                                                          \
    asm volatile("ldmatrix.sync.aligned.m8n8.x4.shared.b16 {%0,%1,%2,%3},[%4];" \
                 : "=r"((r)[0]), "=r"((r)[1]), "=r"((r)[2]), "=r"((r)[3])       \
                 : "r"(addr))
#define LDSM4T(r, addr)                                                         \
    asm volatile("ldmatrix.sync.aligned.m8n8.x4.trans.shared.b16 {%0,%1,%2,%3},[%4];" \
                 : "=r"((r)[0]), "=r"((r)[1]), "=r"((r)[2]), "=r"((r)[3])       \
                 : "r"(addr))
#define MMA_F16(d, a, b0, b1)                                                   \
    asm volatile("mma.sync.aligned.m16n8k16.row.col.f32.f16.f16.f32 "           \
                 "{%0,%1,%2,%3},{%4,%5,%6,%7},{%8,%9},{%0,%1,%2,%3};"           \
                 : "+f"((d)[0]), "+f"((d)[1]), "+f"((d)[2]), "+f"((d)[3])       \
                 : "r"((a)[0]), "r"((a)[1]), "r"((a)[2]), "r"((a)[3]),          \
                   "r"(b0), "r"(b1))

// ---------------- prep 1: pack W (pose ++ act) -> fp16, bias ----------------
__global__ void pack_w(const float* __restrict__ Wp, const float* __restrict__ bp,
                       const float* __restrict__ Wa, const float* __restrict__ ba) {
    int i = blockIdx.x * blockDim.x + threadIdx.x;
    if (i < M_TOT * A_CH) {
        int o = i >> 9;
        int a = i & 511;
        float v = (o < M_POSE) ? Wp[o * A_CH + a] : Wa[(o - M_POSE) * A_CH + a];
        g_W[i] = __float2half_rn(v);
    }
    if (i < M_TOT)
        g_bias[i] = (i < M_POSE) ? bp[i] : ba[i - M_POSE];
}

// ---------------- prep 2: x fp32 -> fp16 (8 elems/thread, 16B stores) ----------------
__global__ __launch_bounds__(256) void conv_x(const float4* __restrict__ x) {
    size_t i = ((size_t)blockIdx.x * blockDim.x + threadIdx.x) * 2;
    float4 v0 = x[i], v1 = x[i + 1];
    __half2 h[4];
    h[0] = __floats2half2_rn(v0.x, v0.y);
    h[1] = __floats2half2_rn(v0.z, v0.w);
    h[2] = __floats2half2_rn(v1.x, v1.y);
    h[3] = __floats2half2_rn(v1.z, v1.w);
    *reinterpret_cast<uint4*>(&g_xh[i * 4]) = *reinterpret_cast<uint4*>(h);
}

// ---------------- fused GEMM: pose tiles (bx<4) + act tile (bx==4), fp16, occ 2 ----------------
// grid (5, 8, 64), 256 threads = 8 warps
__global__ __launch_bounds__(NTHR, 2) void caps_mma(float* __restrict__ out) {
    extern __shared__ char smem[];
    const uint32_t sb = s2u(smem);
    const int tid  = threadIdx.x;
    const int lane = tid & 31, wid = tid >> 5;
    const int hw0 = blockIdx.y * BN;
    const int img = blockIdx.z;
    const bool is_act_cta = (blockIdx.x == 4);
    const int m0 = is_act_cta ? M_POSE : blockIdx.x * BM;

    const char* wptr = (const char*)(g_W + (size_t)m0 * A_CH);              // row = 1024 B
    const char* xptr = (const char*)(g_xh + (size_t)img * A_CH * HW + hw0); // row = 2048 B

    // B-tile loader: 32 rows x 256 B fp16 -> 2 cp16/thread
#define ISSUE_B(s_, kof)                                                        \
    do {                                                                        \
        _Pragma("unroll")                                                       \
        for (int j = 0; j < 2; ++j) {                                           \
            int idx = tid + j * NTHR;                                           \
            int r = idx >> 4, c = idx & 15;                                     \
            uint32_t so = r * B_ROW_B + c * 16;                                 \
            size_t go = (((kof) + r) * (size_t)HW + c * 8) * 2;                 \
            cp16((s_) + OFF_B + so, xptr + go);                                 \
        }                                                                       \
    } while (0)

    if (!is_act_cta) {
        // ============ pose branch: 128 x 128, warp grid 2M x 4N, warp tile 64x32 ============
        const int wm = wid & 1, wn = wid >> 1;   // wn 0..3

        // A loader: 128 rows x 64 B fp16 -> 2 cp16/thread
#define ISSUE(stage, ch)                                                        \
    do {                                                                        \
        uint32_t s_ = sb + (stage) * STG_B;                                     \
        size_t kof = (size_t)(ch) * BK;                                         \
        _Pragma("unroll")                                                       \
        for (int j = 0; j < 2; ++j) {                                           \
            int idx = tid + j * NTHR;                                           \
            int r = idx >> 2, c = idx & 3;                                      \
            uint32_t so = r * A_ROW_B + c * 16;                                 \
            size_t go = ((size_t)r * A_CH + kof) * 2 + c * 16;                  \
            cp16(s_ + OFF_A + so, wptr + go);                                   \
        }                                                                       \
        ISSUE_B(s_, kof);                                                       \
        CP_COMMIT();                                                            \
    } while (0)

        float acc[4][4][4];
#pragma unroll
        for (int i = 0; i < 4; ++i)
#pragma unroll
            for (int j = 0; j < 4; ++j)
#pragma unroll
                for (int k = 0; k < 4; ++k) acc[i][j][k] = 0.f;

        // R7-proven lane mappings
        const uint32_t aLane = (uint32_t)((wm * 64 + (lane & 15)) * A_ROW_B + (lane >> 4) * 16);
        const uint32_t bLane = (uint32_t)((lane & 15) * B_ROW_B + (wn * 32 + (lane >> 4) * 8) * 2);

        ISSUE(0, 0);
        ISSUE(1, 1);

        for (int ch = 0; ch < NCH; ++ch) {
            if (ch == NCH - 1) CP_WAIT(0); else CP_WAIT(1);
            __syncthreads();
            if (ch + 2 < NCH) ISSUE((ch + 2) % NSTAGE, ch + 2);

            const uint32_t s_ = sb + (ch % NSTAGE) * STG_B;
#pragma unroll
            for (int k16 = 0; k16 < 2; ++k16) {
                uint32_t af[4][4];
#pragma unroll
                for (int mt = 0; mt < 4; ++mt) {
                    uint32_t aAddr = s_ + OFF_A + aLane + mt * 16 * A_ROW_B + k16 * 32;
                    LDSM4(af[mt], aAddr);
                }
                uint32_t bh[8];
#pragma unroll
                for (int nt = 0; nt < 2; ++nt) {
                    uint32_t bAddr = s_ + OFF_B + bLane + k16 * 16 * B_ROW_B + nt * 32;
                    LDSM4T(bh + nt * 4, bAddr);
                }
#pragma unroll
                for (int mt = 0; mt < 4; ++mt)
#pragma unroll
                    for (int j = 0; j < 4; ++j) {
                        int bi = (j >> 1) * 4 + (j & 1) * 2;
                        MMA_F16(acc[mt][j], af[mt], bh[bi], bh[bi + 1]);
                    }
            }
        }
#undef ISSUE

        const int hwBase = hw0 + wn * 32 + (lane & 3) * 2;
#pragma unroll
        for (int mt = 0; mt < 4; ++mt) {
#pragma unroll
            for (int rr = 0; rr < 2; ++rr) {
                const int m = m0 + wm * 64 + mt * 16 + (lane >> 2) + rr * 8;
                const float bias = g_bias[m];
                float* rowp = out + ((size_t)img * M_POSE + m) * HW;
#pragma unroll
                for (int j = 0; j < 4; ++j) {
                    float2 v;
                    v.x = acc[mt][j][rr * 2 + 0] + bias;
                    v.y = acc[mt][j][rr * 2 + 1] + bias;
                    *reinterpret_cast<float2*>(rowp + hwBase + j * 8) = v;
                }
            }
        }
    } else {
        // ============ act branch: 32 x 128 + sigmoid; 8 warps, warp tile 32x16 ============
#define AISSUE(stage, ch)                                                       \
    do {                                                                        \
        uint32_t s_ = sb + (stage) * STG_B;                                     \
        size_t kof = (size_t)(ch) * BK;                                         \
        if (tid < 128) {                                                        \
            int r = tid >> 2, c = tid & 3;                                      \
            uint32_t so = r * A_ROW_B + c * 16;                                 \
            size_t go = ((size_t)r * A_CH + kof) * 2 + c * 16;                  \
            cp16(s_ + OFF_A + so, wptr + go);                                   \
        }                                                                       \
        ISSUE_B(s_, kof);                                                       \
        CP_COMMIT();                                                            \
    } while (0)

        float acc[2][2][4];
#pragma unroll
        for (int i = 0; i < 2; ++i)
#pragma unroll
            for (int j = 0; j < 2; ++j)
#pragma unroll
                for (int k = 0; k < 4; ++k) acc[i][j][k] = 0.f;

        const uint32_t aLane = (uint32_t)((lane & 15) * A_ROW_B + (lane >> 4) * 16);
        const uint32_t bLane = (uint32_t)((lane & 15) * B_ROW_B + (wid * 16 + (lane >> 4) * 8) * 2);

        AISSUE(0, 0);
        AISSUE(1, 1);

        for (int ch = 0; ch < NCH; ++ch) {
            if (ch == NCH - 1) CP_WAIT(0); else CP_WAIT(1);
            __syncthreads();
            if (ch + 2 < NCH) AISSUE((ch + 2) % NSTAGE, ch + 2);

            const uint32_t s_ = sb + (ch % NSTAGE) * STG_B;
#pragma unroll
            for (int k16 = 0; k16 < 2; ++k16) {
                uint32_t af[2][4];
#pragma unroll
                for (int mt = 0; mt < 2; ++mt) {
                    uint32_t aAddr = s_ + OFF_A + aLane + mt * 16 * A_ROW_B + k16 * 32;
                    LDSM4(af[mt], aAddr);
                }
                uint32_t bh[4];
                {
                    uint32_t bAddr = s_ + OFF_B + bLane + k16 * 16 * B_ROW_B;
                    LDSM4T(bh, bAddr);
                }
#pragma unroll
                for (int mt = 0; mt < 2; ++mt)
#pragma unroll
                    for (int j = 0; j < 2; ++j)
                        MMA_F16(acc[mt][j], af[mt], bh[j * 2], bh[j * 2 + 1]);
            }
        }
#undef AISSUE

        const int hwBase = hw0 + wid * 16 + (lane & 3) * 2;
        float* actout = out + (size_t)N_IMG * M_POSE * HW;
#pragma unroll
        for (int mt = 0; mt < 2; ++mt) {
#pragma unroll
            for (int rr = 0; rr < 2; ++rr) {
                const int m = mt * 16 + (lane >> 2) + rr * 8;   // 0..31
                const float bias = g_bias[M_POSE + m];
                float* rowp = actout + ((size_t)img * (M_TOT - M_POSE) + m) * HW;
#pragma unroll
                for (int j = 0; j < 2; ++j) {
                    float2 v;
                    v.x = acc[mt][j][rr * 2 + 0] + bias;
                    v.y = acc[mt][j][rr * 2 + 1] + bias;
                    v.x = 1.f / (1.f + __expf(-v.x));
                    v.y = 1.f / (1.f + __expf(-v.y));
                    *reinterpret_cast<float2*>(rowp + hwBase + j * 8) = v;
                }
            }
        }
    }
#undef ISSUE_B
}

// ---------------- launch ----------------
extern "C" void kernel_launch(void* const* d_in, const int* in_sizes, int n_in,
                              void* d_out, int out_size) {
    const float* x  = (const float*)d_in[0];  // [64, 512, 32, 32]
    const float* Wp = (const float*)d_in[1];  // [512, 512]
    const float* bp = (const float*)d_in[2];  // [512]
    const float* Wa = (const float*)d_in[3];  // [32, 512]
    const float* ba = (const float*)d_in[4];  // [32]
    float* out = (float*)d_out;

    pack_w<<<(M_TOT * A_CH + 255) / 256, 256>>>(Wp, bp, Wa, ba);

    size_t total4 = (size_t)N_IMG * A_CH * HW / 4;   // float4 count
    conv_x<<<(unsigned)(total4 / 512), 256>>>((const float4*)x);

    cudaFuncSetAttribute(caps_mma, cudaFuncAttributeMaxDynamicSharedMemorySize, SMEM_MAIN);
    caps_mma<<<dim3(5, HW / BN, N_IMG), NTHR, SMEM_MAIN>>>(out);
}